// round 8
// baseline (speedup 1.0000x reference)
#include <cuda_runtime.h>
#include <cuda_bf16.h>
#include <cstdint>

// Problem constants
#define Bz 8
#define Tz 1024
#define Dz 1024
#define Qz 8
#define Kz 4096
#define dz 128
#define Mz (Bz*Tz)               // 8192 rows
#define OUT_ELEMS (Mz*Dz)        // 8388608
#define IDX_ELEMS (Mz*Qz)        // 65536
#define NQ IDX_ELEMS

#define MARGIN 1.0f
#define CAPT   8                 // per (thread,warp-half) slots; 8 groups/query -> 64

// Scratch (device globals: allocation-free rule)
__device__ float g_xn[(size_t)Mz*Dz];                    // fp32 normed x (exact rescore)
__device__ float g_hc2[Qz*Kz];                           // 0.5*||c||^2 fp32
__device__ int   g_idx[NQ];
__device__ int   g_cnt[NQ*8];                            // per (query, wn*4+t4)
__device__ int   g_cand[(size_t)NQ*64];
// bf16 operands pre-permuted into HMMA fragment order [frag][lane][16B]
__device__ __align__(16) unsigned char g_xb [(size_t)64*8*32768];   // [mtile][q]: 128x128
__device__ __align__(16) unsigned char g_cbb[(size_t)8*32*32768];   // [q][chunk]: 128x128

static __device__ __forceinline__ void cp16s(uint32_t s, const void* g){
    asm volatile("cp.async.cg.shared.global [%0], [%1], 16;" :: "r"(s), "l"(g));
}
static __device__ __forceinline__ void mma_bf16(float* d, const uint32_t* a, uint32_t b0, uint32_t b1){
    asm volatile("mma.sync.aligned.m16n8k16.row.col.f32.bf16.bf16.f32 "
                 "{%0,%1,%2,%3}, {%4,%5,%6,%7}, {%8,%9}, {%0,%1,%2,%3};"
                 : "+f"(d[0]), "+f"(d[1]), "+f"(d[2]), "+f"(d[3])
                 : "r"(a[0]), "r"(a[1]), "r"(a[2]), "r"(a[3]), "r"(b0), "r"(b1));
}
static __device__ __forceinline__ uint32_t bpack(float x, float y){
    __nv_bfloat162 p = __float22bfloat162_rn(make_float2(x, y));
    return *reinterpret_cast<uint32_t*>(&p);
}

// ---------------- Kernel 1: input rmsnorm (+ fragment-order bf16 write) ----------------
__global__ void rmsnorm_in_kernel(const float* __restrict__ x,
                                  const float* __restrict__ w){
    int m = blockIdx.x, tt = threadIdx.x;
    float4 v = reinterpret_cast<const float4*>(x)[(size_t)m*256 + tt];
    float ss = v.x*v.x + v.y*v.y + v.z*v.z + v.w*v.w;
    __shared__ float sred[8];
    __shared__ float s_scale;
    #pragma unroll
    for (int o = 16; o > 0; o >>= 1) ss += __shfl_xor_sync(0xffffffffu, ss, o);
    if ((tt & 31) == 0) sred[tt >> 5] = ss;
    __syncthreads();
    if (tt < 8){
        float s2 = sred[tt];
        #pragma unroll
        for (int o = 4; o > 0; o >>= 1) s2 += __shfl_xor_sync(0xffu, s2, o);
        if (tt == 0){
            float mean = s2 * (1.0f/1024.0f) + 1e-5f;
            float r = rsqrtf(mean);
            r = r * (1.5f - 0.5f*mean*r*r);
            s_scale = r;
        }
    }
    __syncthreads();
    float sc = s_scale;
    float4 wv = reinterpret_cast<const float4*>(w)[tt];
    float4 o4 = make_float4(v.x*sc*wv.x, v.y*sc*wv.y, v.z*sc*wv.z, v.w*sc*wv.w);
    reinterpret_cast<float4*>(g_xn)[(size_t)m*256 + tt] = o4;

    // A fragment image: region (mtile, q); this thread owns row r=m&127, local k0=(tt&31)*4
    int q  = tt >> 5;
    int k0 = (tt & 31) * 4;
    int r  = m & 127;
    int mf = r >> 4, g = r & 7, hh = (r >> 3) & 1;
    int s  = k0 >> 4;
    int kh = (k0 & 15) >> 3;
    int ta = (k0 & 7) >> 1;                 // in {0,2}; pair B goes to ta+1
    int reg = hh + 2*kh;
    unsigned char* base = g_xb + ((size_t)((m >> 7)*8 + q) << 15);
    uint32_t off = (uint32_t)(((mf*8 + s)*32 + g*4 + ta)*16 + reg*4);
    *reinterpret_cast<uint32_t*>(base + off)      = bpack(o4.x, o4.y);
    *reinterpret_cast<uint32_t*>(base + off + 16) = bpack(o4.z, o4.w);
}

// ---------------- Kernel 2: codebook prep: hc2 + fragment-order bf16 B ----------------
__global__ void cbprep_kernel(const float* __restrict__ cb){
    int code = blockIdx.x*8 + (threadIdx.x >> 5);   // 0..32767
    int lane = threadIdx.x & 31;
    float4 c = reinterpret_cast<const float4*>(cb)[(size_t)code*32 + lane];
    float s = c.x*c.x + c.y*c.y + c.z*c.z + c.w*c.w;
    #pragma unroll
    for (int o = 16; o > 0; o >>= 1) s += __shfl_xor_sync(0xffffffffu, s, o);
    if (lane == 0) g_hc2[code] = 0.5f*s;

    int q = code >> 12, n = code & 4095;
    int ch = n >> 7, nl = n & 127;
    int nf = nl >> 3, g = nl & 7;
    int k0 = lane * 4;
    int sp = k0 >> 5;
    int j  = (k0 & 31) >> 3;
    int ta = (k0 & 7) >> 1;                 // in {0,2}
    unsigned char* base = g_cbb + ((size_t)(q*32 + ch) << 15);
    uint32_t off = (uint32_t)(((nf*4 + sp)*32 + g*4 + ta)*16 + j*4);
    *reinterpret_cast<uint32_t*>(base + off)      = bpack(c.x, c.y);
    *reinterpret_cast<uint32_t*>(base + off + 16) = bpack(c.z, c.w);
}

// ---------------- Kernel 3: HMMA screen + candidate collection ----------------
// Block (mtile, q): 128 rows x all 4096 codes in 32 chunks of 128.
// Warp tile 32x64. Appends code n when score > running_top1 - MARGIN.
// Slot ownership: per query 8 groups = (wn*4 + t4), CAPT slots each (collision-free).
#define SM_A   0u
#define SM_B0  32768u
#define SM_B1  65536u
#define SM_HC  98304u
#define SMEM_SCREEN 114688

__global__ void __launch_bounds__(256, 2)
screen_kernel(){
    extern __shared__ __align__(16) unsigned char smem[];
    uint32_t sbase = (uint32_t)__cvta_generic_to_shared(smem);

    int tid = threadIdx.x, w = tid >> 5, L = tid & 31;
    int g5 = L >> 2, t4 = L & 3;
    int wm = w >> 1, wn = w & 1;
    int mt = blockIdx.x, q = blockIdx.y, m0 = mt*128;
    int slotbase = (wn*4 + t4)*CAPT;

    // prologue cp.async: A (32KB), hc2 (16KB), B chunk0 (32KB) -> one group
    const unsigned char* gA = g_xb + ((size_t)(mt*8 + q) << 15);
    #pragma unroll
    for (int i = 0; i < 8; ++i)
        cp16s(sbase + SM_A + (uint32_t)(tid + i*256)*16u, gA + (size_t)(tid + i*256)*16);
    const unsigned char* gH = (const unsigned char*)(g_hc2 + q*Kz);
    #pragma unroll
    for (int i = 0; i < 4; ++i)
        cp16s(sbase + SM_HC + (uint32_t)(tid + i*256)*16u, gH + (size_t)(tid + i*256)*16);
    const unsigned char* gB0 = g_cbb + ((size_t)(q*32) << 15);
    #pragma unroll
    for (int i = 0; i < 8; ++i)
        cp16s(sbase + SM_B0 + (uint32_t)(tid + i*256)*16u, gB0 + (size_t)(tid + i*256)*16);
    asm volatile("cp.async.commit_group;");

    // per row-class state: rc = i*2 + h -> row = m0 + wm*32 + i*16 + h*8 + g5
    float thr[4] = {-3.0e38f, -3.0e38f, -3.0e38f, -3.0e38f};
    int   cnt[4] = {0, 0, 0, 0};
    size_t gq[4];
    #pragma unroll
    for (int rc = 0; rc < 4; ++rc){
        int row = m0 + wm*32 + (rc >> 1)*16 + (rc & 1)*8 + g5;
        gq[rc] = (size_t)row*Qz + q;
    }

    const float* hcs = (const float*)(smem + SM_HC);

    for (int c = 0; c < 32; ++c){
        __syncthreads();            // everyone done reading buf[(c+1)&1] from iter c-1
        if (c + 1 < 32){
            const unsigned char* gB = g_cbb + ((size_t)(q*32 + c + 1) << 15);
            uint32_t dst = sbase + (((c+1) & 1) ? SM_B1 : SM_B0);
            #pragma unroll
            for (int i = 0; i < 8; ++i)
                cp16s(dst + (uint32_t)(tid + i*256)*16u, gB + (size_t)(tid + i*256)*16);
            asm volatile("cp.async.commit_group;");
            asm volatile("cp.async.wait_group 1;");
        } else {
            asm volatile("cp.async.wait_group 0;");
        }
        __syncthreads();            // B[c] visible to all

        float acc[2][8][4];
        #pragma unroll
        for (int i = 0; i < 2; ++i)
            #pragma unroll
            for (int nf = 0; nf < 8; ++nf)
                #pragma unroll
                for (int r = 0; r < 4; ++r) acc[i][nf][r] = 0.0f;

        #pragma unroll
        for (int sp = 0; sp < 4; ++sp){
            uint4 a0e = *reinterpret_cast<const uint4*>(smem + SM_A + (((wm*2+0)*8 + 2*sp    )*32 + L)*16);
            uint4 a0o = *reinterpret_cast<const uint4*>(smem + SM_A + (((wm*2+0)*8 + 2*sp + 1)*32 + L)*16);
            uint4 a1e = *reinterpret_cast<const uint4*>(smem + SM_A + (((wm*2+1)*8 + 2*sp    )*32 + L)*16);
            uint4 a1o = *reinterpret_cast<const uint4*>(smem + SM_A + (((wm*2+1)*8 + 2*sp + 1)*32 + L)*16);
            const unsigned char* bb = smem + ((c & 1) ? SM_B1 : SM_B0);
            #pragma unroll
            for (int nf = 0; nf < 8; ++nf){
                uint4 bq = *reinterpret_cast<const uint4*>(bb + (((wn*8+nf)*4 + sp)*32 + L)*16);
                mma_bf16(acc[0][nf], (const uint32_t*)&a0e, bq.x, bq.y);
                mma_bf16(acc[1][nf], (const uint32_t*)&a1e, bq.x, bq.y);
                mma_bf16(acc[0][nf], (const uint32_t*)&a0o, bq.z, bq.w);
                mma_bf16(acc[1][nf], (const uint32_t*)&a1o, bq.z, bq.w);
            }
        }

        // refresh thresholds across the quad owning these rows (lag <= 1 chunk: safe)
        #pragma unroll
        for (int rc = 0; rc < 4; ++rc){
            float tv = thr[rc];
            tv = fmaxf(tv, __shfl_xor_sync(0xffffffffu, tv, 1));
            tv = fmaxf(tv, __shfl_xor_sync(0xffffffffu, tv, 2));
            thr[rc] = tv;
        }

        // scan: score = xc - 0.5*||c||^2 ; append candidates near the running max
        const float* hcp = hcs + c*128 + wn*64;
        #pragma unroll
        for (int nf = 0; nf < 8; ++nf){
            float2 hv = *reinterpret_cast<const float2*>(hcp + nf*8 + t4*2);
            int n0 = c*128 + wn*64 + nf*8 + t4*2;
            #pragma unroll
            for (int i = 0; i < 2; ++i){
                float v00 = acc[i][nf][0] - hv.x;   // row rc=2i,   col n0
                float v01 = acc[i][nf][1] - hv.y;   // row rc=2i,   col n0+1
                float v10 = acc[i][nf][2] - hv.x;   // row rc=2i+1, col n0
                float v11 = acc[i][nf][3] - hv.y;
                int rc0 = 2*i, rc1 = 2*i + 1;
                if (v00 > thr[rc0]){
                    if (cnt[rc0] < CAPT) g_cand[gq[rc0]*64 + slotbase + cnt[rc0]] = n0;
                    cnt[rc0]++; thr[rc0] = fmaxf(thr[rc0], v00 - MARGIN);
                }
                if (v01 > thr[rc0]){
                    if (cnt[rc0] < CAPT) g_cand[gq[rc0]*64 + slotbase + cnt[rc0]] = n0 + 1;
                    cnt[rc0]++; thr[rc0] = fmaxf(thr[rc0], v01 - MARGIN);
                }
                if (v10 > thr[rc1]){
                    if (cnt[rc1] < CAPT) g_cand[gq[rc1]*64 + slotbase + cnt[rc1]] = n0;
                    cnt[rc1]++; thr[rc1] = fmaxf(thr[rc1], v10 - MARGIN);
                }
                if (v11 > thr[rc1]){
                    if (cnt[rc1] < CAPT) g_cand[gq[rc1]*64 + slotbase + cnt[rc1]] = n0 + 1;
                    cnt[rc1]++; thr[rc1] = fmaxf(thr[rc1], v11 - MARGIN);
                }
            }
        }
    }

    #pragma unroll
    for (int rc = 0; rc < 4; ++rc)
        g_cnt[gq[rc]*8 + wn*4 + t4] = cnt[rc];
}

// ---------------- Kernel 4: exact fp32 rescore of candidates ----------------
__global__ void resolve_kernel(const float* __restrict__ cb, float* __restrict__ tail){
    int gw = blockIdx.x*8 + (threadIdx.x >> 5);     // query id 0..65535
    int lane = threadIdx.x & 31;
    int m = gw >> 3, q = gw & 7;
    float4 xv = reinterpret_cast<const float4*>(g_xn + (size_t)m*Dz + q*dz)[lane];
    int4 ca = *reinterpret_cast<const int4*>(g_cnt + (size_t)gw*8);
    int4 cb4 = *reinterpret_cast<const int4*>(g_cnt + (size_t)gw*8 + 4);
    const float* hq = g_hc2 + q*Kz;
    const float4* cbq = reinterpret_cast<const float4*>(cb + (size_t)q*Kz*dz);
    float bv = -3.4e38f; int bi = 0;
    int cc[8] = {ca.x, ca.y, ca.z, ca.w, cb4.x, cb4.y, cb4.z, cb4.w};
    bool ok = true;
    #pragma unroll
    for (int t = 0; t < 8; ++t) ok = ok && (cc[t] <= CAPT);

    if (ok){
        #pragma unroll
        for (int t = 0; t < 8; ++t){
            for (int i = 0; i < cc[t]; ++i){
                int n = g_cand[(size_t)gw*64 + t*CAPT + i];
                float4 cv = cbq[(size_t)n*32 + lane];
                float p = xv.x*cv.x + xv.y*cv.y + xv.z*cv.z + xv.w*cv.w;
                #pragma unroll
                for (int o = 16; o > 0; o >>= 1) p += __shfl_xor_sync(0xffffffffu, p, o);
                float s = p - hq[n];
                if (s > bv || (s == bv && n < bi)) { bv = s; bi = n; }
            }
        }
    } else {
        // overflow fallback: brute force all codes (rare)
        for (int n = 0; n < Kz; ++n){
            float4 cv = cbq[(size_t)n*32 + lane];
            float p = xv.x*cv.x + xv.y*cv.y + xv.z*cv.z + xv.w*cv.w;
            #pragma unroll
            for (int o = 16; o > 0; o >>= 1) p += __shfl_xor_sync(0xffffffffu, p, o);
            float s = p - hq[n];
            if (s > bv) { bv = s; bi = n; }
        }
    }
    if (lane == 0){
        g_idx[gw] = bi;
        if (tail) tail[gw] = (float)bi;
    }
}

// ---------------- Kernel 5: gather codes + output rmsnorm ----------------
__global__ void out_kernel(const float* __restrict__ cb,
                           const float* __restrict__ w,
                           float* __restrict__ out){
    int m = blockIdx.x, t = threadIdx.x;
    __shared__ int   sidx[8];
    __shared__ float s_scale;
    if (t < 8) sidx[t] = g_idx[m*Qz + t];
    __syncthreads();
    if (t < 8){
        float p = g_hc2[t*Kz + sidx[t]];
        #pragma unroll
        for (int o = 4; o > 0; o >>= 1) p += __shfl_xor_sync(0xffu, p, o);
        if (t == 0){
            float mean = (2.0f*p) * (1.0f/1024.0f) + 1e-5f;
            float r = rsqrtf(mean);
            r = r * (1.5f - 0.5f*mean*r*r);
            s_scale = r;
        }
    }
    __syncthreads();
    int q = t >> 5, lane = t & 31;
    float4 c = reinterpret_cast<const float4*>(cb)[((size_t)q*Kz + sidx[q])*32 + lane];
    float sc = s_scale;
    float4 wv = reinterpret_cast<const float4*>(w)[t];
    reinterpret_cast<float4*>(out)[(size_t)m*256 + t] =
        make_float4(c.x*sc*wv.x, c.y*sc*wv.y, c.z*sc*wv.z, c.w*sc*wv.w);
}

// ---------------- Launch ----------------
extern "C" void kernel_launch(void* const* d_in, const int* in_sizes, int n_in,
                              void* d_out, int out_size){
    const float* x     = (const float*)d_in[0];
    const float* cb    = (const float*)d_in[1];
    const float* w_in  = (const float*)d_in[2];
    const float* w_out = (const float*)d_in[3];
    float* out = (float*)d_out;
    float* tail = (out_size >= OUT_ELEMS + IDX_ELEMS) ? (out + OUT_ELEMS) : nullptr;

    cudaFuncSetAttribute((const void*)screen_kernel,
                         cudaFuncAttributeMaxDynamicSharedMemorySize, SMEM_SCREEN);

    rmsnorm_in_kernel<<<Mz, 256>>>(x, w_in);
    cbprep_kernel<<<(Qz*Kz)/8, 256>>>(cb);
    screen_kernel<<<dim3(64, 8), 256, SMEM_SCREEN>>>();
    resolve_kernel<<<NQ/8, 256>>>(cb, tail);
    out_kernel<<<Mz, 256>>>(cb, w_out, out);
}